// round 16
// baseline (speedup 1.0000x reference)
#include <cuda_runtime.h>
#include <math.h>

// ---------------------------------------------------------------------------
// Problem dims
// ---------------------------------------------------------------------------
#define TOK    4096
#define BATCH  8
#define SEQ    512
#define Dm     256
#define FFd    1024
#define Np     256
#define ENCIN  4096
#define Kc     5

// ---------------------------------------------------------------------------
// Scratch
// ---------------------------------------------------------------------------
__device__ float g_z [TOK * Dm];
__device__ float g_q [TOK * Dm];
__device__ float g_k [TOK * Dm];
__device__ float g_v [TOK * Dm];
__device__ float g_o [TOK * Dm];
__device__ float g_h1[TOK * FFd];
__device__ float g_encpart[32 * Np * 128];
__device__ float g_low[Np * 2];
__device__ float g_hd [Np * 128];
__device__ float g_dsq[Np];
__device__ int   g_idx[Np];
__device__ float g_recpart[Np];

// ---------------------------------------------------------------------------
__device__ __forceinline__ float blockSum256(float v) {
    __shared__ float red[8];
#pragma unroll
    for (int o = 16; o; o >>= 1) v += __shfl_xor_sync(0xffffffffu, v, o);
    if ((threadIdx.x & 31) == 0) red[threadIdx.x >> 5] = v;
    __syncthreads();
    float s = red[0] + red[1] + red[2] + red[3] + red[4] + red[5] + red[6] + red[7];
    __syncthreads();
    return s;
}

__device__ __forceinline__ float blockSum128(float v) {
    __shared__ float red[4];
#pragma unroll
    for (int o = 16; o; o >>= 1) v += __shfl_xor_sync(0xffffffffu, v, o);
    if ((threadIdx.x & 31) == 0) red[threadIdx.x >> 5] = v;
    __syncthreads();
    float s = red[0] + red[1] + red[2] + red[3];
    __syncthreads();
    return s;
}

__device__ __forceinline__ void cpasync16(void* smemp, const void* g) {
    unsigned s = (unsigned)__cvta_generic_to_shared(smemp);
    asm volatile("cp.async.cg.shared.global [%0], [%1], 16;" :: "r"(s), "l"(g));
}

#define MMA_TF32(acc, afr, b0, b1)                                            \
    asm volatile(                                                             \
        "mma.sync.aligned.m16n8k8.row.col.f32.tf32.tf32.f32 "                 \
        "{%0,%1,%2,%3},{%4,%5,%6,%7},{%8,%9},{%0,%1,%2,%3};"                  \
        : "+f"((acc)[0]), "+f"((acc)[1]), "+f"((acc)[2]), "+f"((acc)[3])      \
        : "r"((afr)[0]), "r"((afr)[1]), "r"((afr)[2]), "r"((afr)[3]),         \
          "r"(b0), "r"(b1))

// ---------------------------------------------------------------------------
// Embedding
// ---------------------------------------------------------------------------
__global__ void embed_kernel(const float* __restrict__ x, const float* __restrict__ W,
                             const float* __restrict__ b, float* __restrict__ z) {
    int n = blockIdx.x, d = threadIdx.x;
    float acc = b[d];
#pragma unroll
    for (int f = 0; f < 8; f++) acc += x[n * 8 + f] * W[f * Dm + d];
    z[(size_t)n * Dm + d] = acc;
}

// ---------------------------------------------------------------------------
// TF32 GEMM core: BM=BN=64, BK=64, 128 threads, 2-stage cp.async.
// Same global K accumulation order as BK=32/3-stage => bit-identical.
// Smem/stage: A[64][68] + B[64][72] = 35840B; 2 stages = 71.7KB (3 CTAs/SM).
// ---------------------------------------------------------------------------
#define G3_A (64 * 68)
#define G3_B (64 * 72)
#define G3_STAGE (G3_A + G3_B)
#define GEMM3_SMEM (2 * G3_STAGE * 4)

__device__ __forceinline__ void gemm3_core(
        const float* __restrict__ A, const float* __restrict__ B,
        int N, int K, int bm, int bn, float acc[2][4][4]) {
    extern __shared__ float smem[];
    int tid = threadIdx.x, lane = tid & 31, w = tid >> 5;
    int wr = w >> 1, wc = w & 1;
    int r4 = lane >> 2, a4 = lane & 3;

#pragma unroll
    for (int mt = 0; mt < 2; mt++)
#pragma unroll
        for (int nt = 0; nt < 4; nt++)
#pragma unroll
            for (int c = 0; c < 4; c++) acc[mt][nt][c] = 0.f;

#define G3_LOAD(sidx, k0)                                                     \
    {                                                                         \
        float* Ad = smem + (sidx) * G3_STAGE;                                 \
        float* Bd = Ad + G3_A;                                                \
        _Pragma("unroll")                                                     \
        for (int j = 0; j < 8; j++) {                                         \
            int idx = tid + (j << 7);                                         \
            int row = idx >> 4, cc = (idx & 15) << 2;                         \
            cpasync16(&Ad[row * 68 + cc],                                     \
                      A + (size_t)(bm + row) * K + (k0) + cc);                \
        }                                                                     \
        _Pragma("unroll")                                                     \
        for (int j = 0; j < 8; j++) {                                         \
            int idx = tid + (j << 7);                                         \
            int row = idx >> 4, cc = (idx & 15) << 2;                         \
            cpasync16(&Bd[row * 72 + cc],                                     \
                      B + (size_t)((k0) + row) * N + bn + cc);                \
        }                                                                     \
        asm volatile("cp.async.commit_group;");                               \
    }

    int KT = K >> 6;
    G3_LOAD(0, 0);

    int s = 0;
    for (int kt = 0; kt < KT; kt++) {
        if (kt + 1 < KT) {
            G3_LOAD(s ^ 1, (kt + 1) << 6);
            asm volatile("cp.async.wait_group 1;");
        } else {
            asm volatile("cp.async.wait_group 0;");
        }
        __syncthreads();
        const float* Am = smem + s * G3_STAGE;
        const float* Bm = Am + G3_A;
#pragma unroll
        for (int ks = 0; ks < 8; ks++) {
            int kd = (ks << 3) + a4;
            unsigned afr[2][4];
#pragma unroll
            for (int mt = 0; mt < 2; mt++) {
                int r = wr * 32 + mt * 16 + r4;
                afr[mt][0] = __float_as_uint(Am[r * 68 + kd]);
                afr[mt][1] = __float_as_uint(Am[(r + 8) * 68 + kd]);
                afr[mt][2] = __float_as_uint(Am[r * 68 + kd + 4]);
                afr[mt][3] = __float_as_uint(Am[(r + 8) * 68 + kd + 4]);
            }
#pragma unroll
            for (int nt = 0; nt < 4; nt++) {
                int n = wc * 32 + (nt << 3) + r4;
                unsigned b0 = __float_as_uint(Bm[kd * 72 + n]);
                unsigned b1 = __float_as_uint(Bm[(kd + 4) * 72 + n]);
#pragma unroll
                for (int mt = 0; mt < 2; mt++) MMA_TF32(acc[mt][nt], afr[mt], b0, b1);
            }
        }
        __syncthreads();
        s ^= 1;
    }
#undef G3_LOAD
}

__device__ __forceinline__ void gemm3_store(
        float acc[2][4][4], const float* __restrict__ bias, float* __restrict__ C,
        int N, int bm, int bn, int mode) {
    int tid = threadIdx.x, lane = tid & 31, w = tid >> 5;
    int wr = w >> 1, wc = w & 1;
    int r4 = lane >> 2, a4 = lane & 3;
#pragma unroll
    for (int mt = 0; mt < 2; mt++) {
        int row = bm + wr * 32 + mt * 16 + r4;
#pragma unroll
        for (int nt = 0; nt < 4; nt++) {
            int col = bn + wc * 32 + (nt << 3) + (a4 << 1);
            float bv0 = 0.f, bv1 = 0.f;
            if (mode >= 1) { bv0 = bias[col]; bv1 = bias[col + 1]; }
            float c0 = acc[mt][nt][0] + bv0, c1 = acc[mt][nt][1] + bv1;
            float c2 = acc[mt][nt][2] + bv0, c3 = acc[mt][nt][3] + bv1;
            if (mode == 2) {
                c0 = fmaxf(c0, 0.f); c1 = fmaxf(c1, 0.f);
                c2 = fmaxf(c2, 0.f); c3 = fmaxf(c3, 0.f);
            }
            *(float2*)(C + (size_t)row * N + col)       = make_float2(c0, c1);
            *(float2*)(C + (size_t)(row + 8) * N + col) = make_float2(c2, c3);
        }
    }
}

__global__ void __launch_bounds__(128) gemm3(
        const float* __restrict__ A, const float* __restrict__ B,
        const float* __restrict__ bias, float* __restrict__ C,
        int M, int N, int K, int mode) {
    float acc[2][4][4];
    int bm = blockIdx.y << 6, bn = blockIdx.x << 6;
    gemm3_core(A, B, N, K, bm, bn, acc);
    gemm3_store(acc, bias, C, N, bm, bn, mode);
}

__global__ void __launch_bounds__(128) gemm3_qkv(
        const float* __restrict__ A,
        const float* __restrict__ Wq, const float* __restrict__ Wk,
        const float* __restrict__ Wv,
        float* __restrict__ q, float* __restrict__ k, float* __restrict__ v) {
    const float* B; float* C;
    if (blockIdx.z == 0)      { B = Wq; C = q; }
    else if (blockIdx.z == 1) { B = Wk; C = k; }
    else                      { B = Wv; C = v; }
    float acc[2][4][4];
    int bm = blockIdx.y << 6, bn = blockIdx.x << 6;
    gemm3_core(A, B, Dm, Dm, bm, bn, acc);
    gemm3_store(acc, nullptr, C, Dm, bm, bn, 0);
}

// ---------------------------------------------------------------------------
// Reconstruction loss GEMM (gemm3 core) with L1 epilogue
// ---------------------------------------------------------------------------
__global__ void __launch_bounds__(128) recgemm(
        const float* __restrict__ hd, const float* __restrict__ W2,
        const float* __restrict__ b2, const float* __restrict__ pts,
        float* __restrict__ part) {
    float acc[2][4][4];
    int bm = blockIdx.y << 6, bn = blockIdx.x << 6;
    gemm3_core(hd, W2, ENCIN, 128, bm, bn, acc);

    int tid = threadIdx.x, lane = tid & 31, w = tid >> 5;
    int wr = w >> 1, wc = w & 1;
    int r4 = lane >> 2, a4 = lane & 3;
    float local = 0.f;
#pragma unroll
    for (int mt = 0; mt < 2; mt++) {
        int row = bm + wr * 32 + mt * 16 + r4;
#pragma unroll
        for (int nt = 0; nt < 4; nt++) {
            int col = bn + wc * 32 + (nt << 3) + (a4 << 1);
            float bv0 = b2[col], bv1 = b2[col + 1];
            float2 p0 = *(const float2*)(pts + (size_t)row * ENCIN + col);
            float2 p1 = *(const float2*)(pts + (size_t)(row + 8) * ENCIN + col);
            local += fabsf(p0.x - (acc[mt][nt][0] + bv0));
            local += fabsf(p0.y - (acc[mt][nt][1] + bv1));
            local += fabsf(p1.x - (acc[mt][nt][2] + bv0));
            local += fabsf(p1.y - (acc[mt][nt][3] + bv1));
        }
    }
    float s = blockSum128(local);
    if (tid == 0) part[blockIdx.y * gridDim.x + blockIdx.x] = s;
}

// ---------------------------------------------------------------------------
// Fused GEMM + residual + LayerNorm (R15-proven): BM=32, BN=256, BK=64,
// 2-stage, 8 warps, grid 128.
// ---------------------------------------------------------------------------
#define GLN_A (32 * 68)
#define GLN_B (64 * 264)
#define GLN_STAGE (GLN_A + GLN_B)
#define GLN_SMEM (2 * GLN_STAGE * 4)

__global__ void __launch_bounds__(256) gemmLN(
        const float* __restrict__ A, const float* __restrict__ W,
        const float* __restrict__ bias, float* __restrict__ z,
        const float* __restrict__ gam, const float* __restrict__ bet, int K) {
    extern __shared__ float smem[];
    int tid = threadIdx.x, lane = tid & 31, w = tid >> 5;
    int wr = w >> 2, wc = w & 3;
    int r4 = lane >> 2, a4 = lane & 3;
    int bm = blockIdx.x << 5;

    float acc[8][4];
#pragma unroll
    for (int nt = 0; nt < 8; nt++)
#pragma unroll
        for (int c = 0; c < 4; c++) acc[nt][c] = 0.f;

#define GLN_LOAD(sidx, k0)                                                    \
    {                                                                         \
        float* Ad = smem + (sidx) * GLN_STAGE;                                \
        float* Bd = Ad + GLN_A;                                               \
        _Pragma("unroll")                                                     \
        for (int j = 0; j < 2; j++) {                                         \
            int idx = tid + (j << 8);                                         \
            int row = idx >> 4, cc = (idx & 15) << 2;                         \
            cpasync16(&Ad[row * 68 + cc],                                     \
                      A + (size_t)(bm + row) * K + (k0) + cc);                \
        }                                                                     \
        _Pragma("unroll")                                                     \
        for (int j = 0; j < 16; j++) {                                        \
            int idx = tid + (j << 8);                                         \
            int row = idx >> 6, cc = (idx & 63) << 2;                         \
            cpasync16(&Bd[row * 264 + cc],                                    \
                      W + (size_t)((k0) + row) * Dm + cc);                    \
        }                                                                     \
        asm volatile("cp.async.commit_group;");                               \
    }

    int KT = K >> 6;
    GLN_LOAD(0, 0);

    int s = 0;
    for (int kt = 0; kt < KT; kt++) {
        if (kt + 1 < KT) {
            GLN_LOAD(s ^ 1, (kt + 1) << 6);
            asm volatile("cp.async.wait_group 1;");
        } else {
            asm volatile("cp.async.wait_group 0;");
        }
        __syncthreads();
        const float* Am = smem + s * GLN_STAGE;
        const float* Bm = Am + GLN_A;
#pragma unroll
        for (int ks = 0; ks < 8; ks++) {
            int kd = (ks << 3) + a4;
            unsigned afr[4];
            int r = wr * 16 + r4;
            afr[0] = __float_as_uint(Am[r * 68 + kd]);
            afr[1] = __float_as_uint(Am[(r + 8) * 68 + kd]);
            afr[2] = __float_as_uint(Am[r * 68 + kd + 4]);
            afr[3] = __float_as_uint(Am[(r + 8) * 68 + kd + 4]);
#pragma unroll
            for (int nt = 0; nt < 8; nt++) {
                int n = wc * 64 + (nt << 3) + r4;
                unsigned b0 = __float_as_uint(Bm[kd * 264 + n]);
                unsigned b1 = __float_as_uint(Bm[(kd + 4) * 264 + n]);
                MMA_TF32(acc[nt], afr, b0, b1);
            }
        }
        __syncthreads();
        s ^= 1;
    }
#undef GLN_LOAD

    int row0 = bm + wr * 16 + r4;
    int row1 = row0 + 8;
    int rl0 = wr * 16 + r4, rl1 = rl0 + 8;
    float v0[16], v1[16];
    float s0 = 0.f, s1 = 0.f;
#pragma unroll
    for (int nt = 0; nt < 8; nt++) {
        int col = wc * 64 + (nt << 3) + (a4 << 1);
        float bb0 = 0.f, bb1 = 0.f;
        if (bias) { bb0 = bias[col]; bb1 = bias[col + 1]; }
        float2 z0 = *(const float2*)(z + (size_t)row0 * Dm + col);
        float2 z1 = *(const float2*)(z + (size_t)row1 * Dm + col);
        float a0 = acc[nt][0] + bb0 + z0.x;
        float a1 = acc[nt][1] + bb1 + z0.y;
        float a2 = acc[nt][2] + bb0 + z1.x;
        float a3 = acc[nt][3] + bb1 + z1.y;
        v0[nt * 2] = a0; v0[nt * 2 + 1] = a1;
        v1[nt * 2] = a2; v1[nt * 2 + 1] = a3;
        s0 += a0 + a1; s1 += a2 + a3;
    }
    s0 += __shfl_xor_sync(0xffffffffu, s0, 1);
    s0 += __shfl_xor_sync(0xffffffffu, s0, 2);
    s1 += __shfl_xor_sync(0xffffffffu, s1, 1);
    s1 += __shfl_xor_sync(0xffffffffu, s1, 2);
    float* red = smem;
    if (a4 == 0) { red[rl0 * 4 + wc] = s0; red[rl1 * 4 + wc] = s1; }
    __syncthreads();
    float mu0 = (red[rl0 * 4] + red[rl0 * 4 + 1] + red[rl0 * 4 + 2] + red[rl0 * 4 + 3]) * (1.f / 256.f);
    float mu1 = (red[rl1 * 4] + red[rl1 * 4 + 1] + red[rl1 * 4 + 2] + red[rl1 * 4 + 3]) * (1.f / 256.f);
    __syncthreads();
    float q0 = 0.f, q1 = 0.f;
#pragma unroll
    for (int i = 0; i < 16; i++) {
        float d0 = v0[i] - mu0, d1 = v1[i] - mu1;
        q0 += d0 * d0; q1 += d1 * d1;
    }
    q0 += __shfl_xor_sync(0xffffffffu, q0, 1);
    q0 += __shfl_xor_sync(0xffffffffu, q0, 2);
    q1 += __shfl_xor_sync(0xffffffffu, q1, 1);
    q1 += __shfl_xor_sync(0xffffffffu, q1, 2);
    if (a4 == 0) { red[rl0 * 4 + wc] = q0; red[rl1 * 4 + wc] = q1; }
    __syncthreads();
    float var0 = (red[rl0 * 4] + red[rl0 * 4 + 1] + red[rl0 * 4 + 2] + red[rl0 * 4 + 3]) * (1.f / 256.f);
    float var1 = (red[rl1 * 4] + red[rl1 * 4 + 1] + red[rl1 * 4 + 2] + red[rl1 * 4 + 3]) * (1.f / 256.f);
    float rs0 = rsqrtf(var0 + 1e-5f), rs1 = rsqrtf(var1 + 1e-5f);
#pragma unroll
    for (int nt = 0; nt < 8; nt++) {
        int col = wc * 64 + (nt << 3) + (a4 << 1);
        float g0 = gam[col], g1 = gam[col + 1];
        float be0 = bet[col], be1 = bet[col + 1];
        *(float2*)(z + (size_t)row0 * Dm + col) = make_float2(
            (v0[nt * 2] - mu0) * rs0 * g0 + be0,
            (v0[nt * 2 + 1] - mu0) * rs0 * g1 + be1);
        *(float2*)(z + (size_t)row1 * Dm + col) = make_float2(
            (v1[nt * 2] - mu1) * rs1 * g0 + be0,
            (v1[nt * 2 + 1] - mu1) * rs1 * g1 + be1);
    }
}

// ---------------------------------------------------------------------------
// TF32-MMA flash attention, chunked-PV small-smem (proven R10)
// ---------------------------------------------------------------------------
#define AT4_SMEM_FLOATS (64 * 36 + 128 * 36 + 128 * 40 + 4 * 192)
#define AT4_SMEM_BYTES  (AT4_SMEM_FLOATS * 4)

__global__ void __launch_bounds__(128, 4) attn4(
        const float* __restrict__ qg, const float* __restrict__ kg,
        const float* __restrict__ vg, float* __restrict__ og) {
    extern __shared__ float sm[];
    float* Qs = sm;
    float* Ks = Qs + 64 * 36;
    float* Vs = Ks + 128 * 36;
    float* Ps = Vs + 128 * 40;

    int bh = blockIdx.y, b = bh >> 3, h = bh & 7;
    int qt = blockIdx.x;
    int tid = threadIdx.x, w = tid >> 5, lane = tid & 31;
    int r4 = lane >> 2, a4 = lane & 3;
    size_t base = (size_t)b * SEQ * Dm + h * 32;
    const float scale = 0.17677669529663687f;

    for (int i = tid; i < 512; i += 128) {
        int row = i >> 3, c4 = (i & 7) << 2;
        float4 t = *(const float4*)(qg + base + (size_t)(qt * 64 + row) * Dm + c4);
        t.x *= scale; t.y *= scale; t.z *= scale; t.w *= scale;
        *(float4*)&Qs[row * 36 + c4] = t;
    }

    int q0 = w * 16;
    float* Pws = Ps + w * 192;
    float m0 = -1e30f, m1 = -1e30f, l0 = 0.f, l1 = 0.f;
    float oacc[4][4];
#pragma unroll
    for (int nt = 0; nt < 4; nt++)
#pragma unroll
        for (int c = 0; c < 4; c++) oacc[nt][c] = 0.f;

    for (int c = 0; c < 4; c++) {
        __syncthreads();
        for (int i = tid; i < 1024; i += 128) {
            int row = i >> 3, c4 = (i & 7) << 2;
            size_t goff = base + (size_t)(c * 128 + row) * Dm + c4;
            float4 tk = *(const float4*)(kg + goff);
            *(float4*)&Ks[row * 36 + c4] = tk;
            float4 tv = *(const float4*)(vg + goff);
            *(float4*)&Vs[row * 40 + c4] = tv;
        }
        __syncthreads();

        float S[16][4];
#pragma unroll
        for (int nt = 0; nt < 16; nt++)
#pragma unroll
            for (int j = 0; j < 4; j++) S[nt][j] = 0.f;

#pragma unroll
        for (int ks = 0; ks < 4; ks++) {
            int kd = (ks << 3) + a4;
            unsigned aq[4];
            int r = q0 + r4;
            aq[0] = __float_as_uint(Qs[r * 36 + kd]);
            aq[1] = __float_as_uint(Qs[(r + 8) * 36 + kd]);
            aq[2] = __float_as_uint(Qs[r * 36 + kd + 4]);
            aq[3] = __float_as_uint(Qs[(r + 8) * 36 + kd + 4]);
#pragma unroll
            for (int nt = 0; nt < 16; nt++) {
                int key = (nt << 3) + r4;
                unsigned b0 = __float_as_uint(Ks[key * 36 + kd]);
                unsigned b1 = __float_as_uint(Ks[key * 36 + kd + 4]);
                MMA_TF32(S[nt], aq, b0, b1);
            }
        }

        float mxa = -1e30f, mxb = -1e30f;
#pragma unroll
        for (int nt = 0; nt < 16; nt++) {
            mxa = fmaxf(mxa, fmaxf(S[nt][0], S[nt][1]));
            mxb = fmaxf(mxb, fmaxf(S[nt][2], S[nt][3]));
        }
#pragma unroll
        for (int off = 1; off < 4; off <<= 1) {
            mxa = fmaxf(mxa, __shfl_xor_sync(0xffffffffu, mxa, off));
            mxb = fmaxf(mxb, __shfl_xor_sync(0xffffffffu, mxb, off));
        }
        float mna = fmaxf(m0, mxa), mnb = fmaxf(m1, mxb);
        float corra = __expf(m0 - mna), corrb = __expf(m1 - mnb);
        float sa = 0.f, sb = 0.f;
#pragma unroll
        for (int nt = 0; nt < 16; nt++) {
            float p0 = __expf(S[nt][0] - mna);
            float p1 = __expf(S[nt][1] - mna);
            float p2 = __expf(S[nt][2] - mnb);
            float p3 = __expf(S[nt][3] - mnb);
            sa += p0 + p1; sb += p2 + p3;
            S[nt][0] = p0; S[nt][1] = p1; S[nt][2] = p2; S[nt][3] = p3;
        }
#pragma unroll
        for (int off = 1; off < 4; off <<= 1) {
            sa += __shfl_xor_sync(0xffffffffu, sa, off);
            sb += __shfl_xor_sync(0xffffffffu, sb, off);
        }
        l0 = l0 * corra + sa; m0 = mna;
        l1 = l1 * corrb + sb; m1 = mnb;
#pragma unroll
        for (int nt = 0; nt < 4; nt++) {
            oacc[nt][0] *= corra; oacc[nt][1] *= corra;
            oacc[nt][2] *= corrb; oacc[nt][3] *= corrb;
        }
        __syncwarp();

#pragma unroll
        for (int ks = 0; ks < 16; ks++) {
            *(float2*)&Pws[r4 * 12 + (a4 << 1)]       = make_float2(S[ks][0], S[ks][1]);
            *(float2*)&Pws[(r4 + 8) * 12 + (a4 << 1)] = make_float2(S[ks][2], S[ks][3]);
            __syncwarp();
            unsigned ap[4];
            ap[0] = __float_as_uint(Pws[r4 * 12 + a4]);
            ap[1] = __float_as_uint(Pws[(r4 + 8) * 12 + a4]);
            ap[2] = __float_as_uint(Pws[r4 * 12 + a4 + 4]);
            ap[3] = __float_as_uint(Pws[(r4 + 8) * 12 + a4 + 4]);
            int keyb = ks << 3;
#pragma unroll
            for (int nt = 0; nt < 4; nt++) {
                int dim = (nt << 3) + r4;
                unsigned b0 = __float_as_uint(Vs[(keyb + a4) * 40 + dim]);
                unsigned b1 = __float_as_uint(Vs[(keyb + a4 + 4) * 40 + dim]);
                MMA_TF32(oacc[nt], ap, b0, b1);
            }
            __syncwarp();
        }
    }

    float inva = 1.f / l0, invb = 1.f / l1;
    int rowa = qt * 64 + q0 + r4;
#pragma unroll
    for (int nt = 0; nt < 4; nt++) {
        int col = (nt << 3) + (a4 << 1);
        *(float2*)(og + base + (size_t)rowa * Dm + col) =
            make_float2(oacc[nt][0] * inva, oacc[nt][1] * inva);
        *(float2*)(og + base + (size_t)(rowa + 8) * Dm + col) =
            make_float2(oacc[nt][2] * invb, oacc[nt][3] * invb);
    }
}

// ---------------------------------------------------------------------------
// fp32 split-K GEMM (encoder path — exact)
// ---------------------------------------------------------------------------
__global__ void __launch_bounds__(256) gemm_splitk(
        const float* __restrict__ A, int lda, const float* __restrict__ B, int ldb,
        float* __restrict__ Cp, int M, int N, int Kchunk) {
    __shared__ float As[16][65];
    __shared__ float Bs[16][64];
    int zc = blockIdx.z;
    A  += zc * Kchunk;
    B  += (size_t)zc * Kchunk * ldb;
    Cp += (size_t)zc * M * N;
    int tid = threadIdx.x;
    int bm = blockIdx.y << 6, bn = blockIdx.x << 6;
    int tx = tid & 15, ty = tid >> 4;
    int arow = tid >> 2, acol = (tid & 3) << 2;
    int brow = tid >> 4, bcol = (tid & 15) << 2;

    float acc[4][4] = {};
    for (int k0 = 0; k0 < Kchunk; k0 += 16) {
        float4 a4 = *(const float4*)(A + (size_t)(bm + arow) * lda + k0 + acol);
        As[acol + 0][arow] = a4.x; As[acol + 1][arow] = a4.y;
        As[acol + 2][arow] = a4.z; As[acol + 3][arow] = a4.w;
        float4 b4 = *(const float4*)(B + (size_t)(k0 + brow) * ldb + bn + bcol);
        *(float4*)&Bs[brow][bcol] = b4;
        __syncthreads();
#pragma unroll
        for (int kk = 0; kk < 16; kk++) {
            float a0 = As[kk][(ty << 2) + 0], a1 = As[kk][(ty << 2) + 1];
            float a2 = As[kk][(ty << 2) + 2], a3 = As[kk][(ty << 2) + 3];
            float4 b = *(const float4*)&Bs[kk][tx << 2];
            acc[0][0] += a0 * b.x; acc[0][1] += a0 * b.y; acc[0][2] += a0 * b.z; acc[0][3] += a0 * b.w;
            acc[1][0] += a1 * b.x; acc[1][1] += a1 * b.y; acc[1][2] += a1 * b.z; acc[1][3] += a1 * b.w;
            acc[2][0] += a2 * b.x; acc[2][1] += a2 * b.y; acc[2][2] += a2 * b.z; acc[2][3] += a2 * b.w;
            acc[3][0] += a3 * b.x; acc[3][1] += a3 * b.y; acc[3][2] += a3 * b.z; acc[3][3] += a3 * b.w;
        }
        __syncthreads();
    }
#pragma unroll
    for (int i = 0; i < 4; i++) {
        float4 r = make_float4(acc[i][0], acc[i][1], acc[i][2], acc[i][3]);
        *(float4*)(Cp + (size_t)(bm + (ty << 2) + i) * N + bn + (tx << 2)) = r;
    }
}

// ---------------------------------------------------------------------------
// Fused enc_reduce + low head (proven R10): one CTA per point.
// ---------------------------------------------------------------------------
__global__ void __launch_bounds__(128) enclow_kernel(
        const float* __restrict__ part, const float* __restrict__ eb1,
        const float* __restrict__ eW2, const float* __restrict__ eb2,
        const float* __restrict__ dW1, const float* __restrict__ db1,
        const float* __restrict__ ctr,
        float* __restrict__ low, float* __restrict__ hd,
        int* __restrict__ idxp, float* __restrict__ dsq) {
    int n = blockIdx.x, m = threadIdx.x;
    __shared__ float lo_sh[2];
    float s = eb1[m];
#pragma unroll
    for (int ch = 0; ch < 32; ch++) s += part[ch * (Np * 128) + n * 128 + m];
    float hv = fmaxf(s, 0.f);

    float pa0 = hv * eW2[m * 2];
    float pa1 = hv * eW2[m * 2 + 1];
    float a0 = blockSum128(pa0);
    float a1 = blockSum128(pa1);
    if (m == 0) {
        float lo0 = 1.f / (1.f + expf(-(a0 + eb2[0])));
        float lo1 = 1.f / (1.f + expf(-(a1 + eb2[1])));
        lo_sh[0] = lo0; lo_sh[1] = lo1;
        low[n * 2 + 0] = lo0;
        low[n * 2 + 1] = lo1;
        int best = 0; float bd = 3.4e38f;
#pragma unroll
        for (int c = 0; c < Kc; c++) {
            float dx = lo0 - ctr[2 * c], dy = lo1 - ctr[2 * c + 1];
            float d2 = dx * dx + dy * dy;
            if (d2 < bd) { bd = d2; best = c; }
        }
        idxp[n] = best;
        dsq[n] = bd;
    }
    __syncthreads();
    float lo0 = lo_sh[0], lo1 = lo_sh[1];
    hd[n * 128 + m] = fmaxf(lo0 * dW1[m] + lo1 * dW1[128 + m] + db1[m], 0.f);
}

// ---------------------------------------------------------------------------
// Final losses + output
// ---------------------------------------------------------------------------
__global__ void final_kernel(const float* __restrict__ dsq, const int* __restrict__ idxp,
                             const float* __restrict__ low, const float* __restrict__ recpart,
                             float* __restrict__ out, int out_size) {
    __shared__ float sums[Kc], cnts[Kc];
    int tid = threadIdx.x;
    float d = dsq[tid];
    int my = idxp[tid];

    float inter = blockSum256(d) * (1.f / 256.f);

    if (tid < Kc) { sums[tid] = 0.f; cnts[tid] = 0.f; }
    __syncthreads();
    atomicAdd(&sums[my], d);
    atomicAdd(&cnts[my], 1.f);
    __syncthreads();

    bool mem = false;
    for (int j = 0; j < 256; j++) {
        if (idxp[j] == tid) { mem = true; break; }
    }
    float arr = mem ? 100.f : 0.f;

    float se = blockSum256(expf(arr - 100.f));
    float lse = logf(se) + 100.f;
    float logp = arr - lse;

    float klsum = blockSum256(-logf(256.f) - logp);
    float kl = klsum * (1.f / (256.f * 256.f));

    float rec = blockSum256(recpart[tid]) * (1.f / (256.f * 4096.f));

    if (tid == 0) {
        float intra = 0.f, ne = 0.f;
#pragma unroll
        for (int c = 0; c < Kc; c++) {
            if (cnts[c] > 0.f) { intra += sums[c] / fmaxf(cnts[c], 1.f); ne += 1.f; }
        }
        intra /= fmaxf(ne, 1.f);
        float loss = inter + intra + kl + rec;
        if (out_size > 0) out[0] = loss;
        if (out_size > 1) out[1] = kl;
    }
    if (2 + tid < out_size) out[2 + tid] = (float)my;
    int p0 = 258 + 2 * tid;
    if (p0 < out_size)     out[p0]     = low[2 * tid];
    if (p0 + 1 < out_size) out[p0 + 1] = low[2 * tid + 1];
}

// ---------------------------------------------------------------------------
// Host launcher
// ---------------------------------------------------------------------------
extern "C" void kernel_launch(void* const* d_in, const int* in_sizes, int n_in,
                              void* d_out, int out_size) {
    const float* x_seg  = (const float*)d_in[1];
    const float* emb_W  = (const float*)d_in[2];
    const float* emb_b  = (const float*)d_in[3];
    const float* Wq     = (const float*)d_in[4];
    const float* Wk     = (const float*)d_in[5];
    const float* Wv     = (const float*)d_in[6];
    const float* Wo     = (const float*)d_in[7];
    const float* W1     = (const float*)d_in[8];
    const float* b1     = (const float*)d_in[9];
    const float* W2     = (const float*)d_in[10];
    const float* b2     = (const float*)d_in[11];
    const float* ln1_g  = (const float*)d_in[12];
    const float* ln1_b  = (const float*)d_in[13];
    const float* ln2_g  = (const float*)d_in[14];
    const float* ln2_b  = (const float*)d_in[15];
    const float* enc_W1 = (const float*)d_in[16];
    const float* enc_b1 = (const float*)d_in[17];
    const float* enc_W2 = (const float*)d_in[18];
    const float* enc_b2 = (const float*)d_in[19];
    const float* dec_W1 = (const float*)d_in[20];
    const float* dec_b1 = (const float*)d_in[21];
    const float* dec_W2 = (const float*)d_in[22];
    const float* dec_b2 = (const float*)d_in[23];
    const float* centers = (const float*)d_in[24];

    float *z, *q, *k, *v, *o, *h1, *encpart, *low, *hd, *dsq, *recpart;
    int* idxp;
    cudaGetSymbolAddress((void**)&z,   g_z);
    cudaGetSymbolAddress((void**)&q,   g_q);
    cudaGetSymbolAddress((void**)&k,   g_k);
    cudaGetSymbolAddress((void**)&v,   g_v);
    cudaGetSymbolAddress((void**)&o,   g_o);
    cudaGetSymbolAddress((void**)&h1,  g_h1);
    cudaGetSymbolAddress((void**)&encpart, g_encpart);
    cudaGetSymbolAddress((void**)&low, g_low);
    cudaGetSymbolAddress((void**)&hd,  g_hd);
    cudaGetSymbolAddress((void**)&dsq, g_dsq);
    cudaGetSymbolAddress((void**)&idxp, g_idx);
    cudaGetSymbolAddress((void**)&recpart, g_recpart);

    cudaFuncSetAttribute(gemm3,     cudaFuncAttributeMaxDynamicSharedMemorySize, GEMM3_SMEM);
    cudaFuncSetAttribute(gemm3_qkv, cudaFuncAttributeMaxDynamicSharedMemorySize, GEMM3_SMEM);
    cudaFuncSetAttribute(recgemm,   cudaFuncAttributeMaxDynamicSharedMemorySize, GEMM3_SMEM);
    cudaFuncSetAttribute(gemmLN,    cudaFuncAttributeMaxDynamicSharedMemorySize, GLN_SMEM);
    cudaFuncSetAttribute(attn4,     cudaFuncAttributeMaxDynamicSharedMemorySize, AT4_SMEM_BYTES);

    embed_kernel<<<TOK, 256>>>(x_seg, emb_W, emb_b, z);

    for (int l = 0; l < 2; l++) {
        size_t wo = (size_t)l * Dm * Dm;
        gemm3_qkv<<<dim3(4, 64, 3), 128, GEMM3_SMEM>>>(z, Wq + wo, Wk + wo, Wv + wo, q, k, v);
        attn4<<<dim3(8, 64), 128, AT4_SMEM_BYTES>>>(q, k, v, o);
        gemmLN<<<128, 256, GLN_SMEM>>>(o, Wo + wo, nullptr, z,
                                       ln1_g + l * Dm, ln1_b + l * Dm, Dm);
        gemm3<<<dim3(16, 64), 128, GEMM3_SMEM>>>(z, W1 + (size_t)l * Dm * FFd, b1 + l * FFd,
                                                 h1, TOK, FFd, Dm, 2);
        gemmLN<<<128, 256, GLN_SMEM>>>(h1, W2 + (size_t)l * FFd * Dm, b2 + l * Dm, z,
                                       ln2_g + l * Dm, ln2_b + l * Dm, FFd);
    }

    gemm_splitk<<<dim3(2, 4, 32), 256>>>(z, ENCIN, enc_W1, 128, encpart, Np, 128, 128);
    enclow_kernel<<<Np, 128>>>(encpart, enc_b1, enc_W2, enc_b2, dec_W1, dec_b1,
                               centers, low, hd, idxp, dsq);
    recgemm<<<dim3(64, 4), 128, GEMM3_SMEM>>>(hd, dec_W2, dec_b2, z, recpart);
    final_kernel<<<1, 256>>>(dsq, idxp, low, recpart, (float*)d_out, out_size);
}

// round 17
// speedup vs baseline: 1.0395x; 1.0395x over previous
#include <cuda_runtime.h>
#include <math.h>

// ---------------------------------------------------------------------------
// Problem dims
// ---------------------------------------------------------------------------
#define TOK    4096
#define BATCH  8
#define SEQ    512
#define Dm     256
#define FFd    1024
#define Np     256
#define ENCIN  4096
#define Kc     5

// ---------------------------------------------------------------------------
// Scratch
// ---------------------------------------------------------------------------
__device__ float g_z [TOK * Dm];
__device__ float g_q [TOK * Dm];
__device__ float g_k [TOK * Dm];
__device__ float g_v [TOK * Dm];
__device__ float g_o [TOK * Dm];
__device__ float g_h1[TOK * FFd];
__device__ float g_encpart[32 * Np * 128];
__device__ float g_low[Np * 2];
__device__ float g_hd [Np * 128];
__device__ float g_dsq[Np];
__device__ int   g_idx[Np];
__device__ float g_recpart[Np];

// ---------------------------------------------------------------------------
__device__ __forceinline__ float blockSum256(float v) {
    __shared__ float red[8];
#pragma unroll
    for (int o = 16; o; o >>= 1) v += __shfl_xor_sync(0xffffffffu, v, o);
    if ((threadIdx.x & 31) == 0) red[threadIdx.x >> 5] = v;
    __syncthreads();
    float s = red[0] + red[1] + red[2] + red[3] + red[4] + red[5] + red[6] + red[7];
    __syncthreads();
    return s;
}

__device__ __forceinline__ float blockSum128(float v) {
    __shared__ float red[4];
#pragma unroll
    for (int o = 16; o; o >>= 1) v += __shfl_xor_sync(0xffffffffu, v, o);
    if ((threadIdx.x & 31) == 0) red[threadIdx.x >> 5] = v;
    __syncthreads();
    float s = red[0] + red[1] + red[2] + red[3];
    __syncthreads();
    return s;
}

__device__ __forceinline__ void cpasync16(void* smemp, const void* g) {
    unsigned s = (unsigned)__cvta_generic_to_shared(smemp);
    asm volatile("cp.async.cg.shared.global [%0], [%1], 16;" :: "r"(s), "l"(g));
}

#define MMA_TF32(acc, afr, b0, b1)                                            \
    asm volatile(                                                             \
        "mma.sync.aligned.m16n8k8.row.col.f32.tf32.tf32.f32 "                 \
        "{%0,%1,%2,%3},{%4,%5,%6,%7},{%8,%9},{%0,%1,%2,%3};"                  \
        : "+f"((acc)[0]), "+f"((acc)[1]), "+f"((acc)[2]), "+f"((acc)[3])      \
        : "r"((afr)[0]), "r"((afr)[1]), "r"((afr)[2]), "r"((afr)[3]),         \
          "r"(b0), "r"(b1))

// ---------------------------------------------------------------------------
// Embedding
// ---------------------------------------------------------------------------
__global__ void embed_kernel(const float* __restrict__ x, const float* __restrict__ W,
                             const float* __restrict__ b, float* __restrict__ z) {
    int n = blockIdx.x, d = threadIdx.x;
    float acc = b[d];
#pragma unroll
    for (int f = 0; f < 8; f++) acc += x[n * 8 + f] * W[f * Dm + d];
    z[(size_t)n * Dm + d] = acc;
}

// ---------------------------------------------------------------------------
// TF32 GEMM core (R15-proven): BM=BN=64, BK=32, 128 threads, 3-stage cp.async.
// ---------------------------------------------------------------------------
#define G3_A (64 * 36)
#define G3_B (32 * 72)
#define G3_STAGE (G3_A + G3_B)
#define GEMM3_SMEM (3 * G3_STAGE * 4)

__device__ __forceinline__ void gemm3_core(
        const float* __restrict__ A, const float* __restrict__ B,
        int N, int K, int bm, int bn, float acc[2][4][4]) {
    extern __shared__ float smem[];
    int tid = threadIdx.x, lane = tid & 31, w = tid >> 5;
    int wr = w >> 1, wc = w & 1;
    int r4 = lane >> 2, a4 = lane & 3;

#pragma unroll
    for (int mt = 0; mt < 2; mt++)
#pragma unroll
        for (int nt = 0; nt < 4; nt++)
#pragma unroll
            for (int c = 0; c < 4; c++) acc[mt][nt][c] = 0.f;

#define G3_LOAD(sidx, k0)                                                     \
    {                                                                         \
        float* Ad = smem + (sidx) * G3_STAGE;                                 \
        float* Bd = Ad + G3_A;                                                \
        _Pragma("unroll")                                                     \
        for (int j = 0; j < 4; j++) {                                         \
            int idx = tid + (j << 7);                                         \
            int row = idx >> 3, cc = (idx & 7) << 2;                          \
            cpasync16(&Ad[row * 36 + cc],                                     \
                      A + (size_t)(bm + row) * K + (k0) + cc);                \
        }                                                                     \
        _Pragma("unroll")                                                     \
        for (int j = 0; j < 4; j++) {                                         \
            int idx = tid + (j << 7);                                         \
            int row = idx >> 4, cc = (idx & 15) << 2;                         \
            cpasync16(&Bd[row * 72 + cc],                                     \
                      B + (size_t)((k0) + row) * N + bn + cc);                \
        }                                                                     \
        asm volatile("cp.async.commit_group;");                               \
    }

    int KT = K >> 5;
    G3_LOAD(0, 0);
    if (KT > 1) G3_LOAD(1, 32);

    int s = 0;
    for (int kt = 0; kt < KT; kt++) {
        if (kt + 1 < KT) asm volatile("cp.async.wait_group 1;");
        else             asm volatile("cp.async.wait_group 0;");
        __syncthreads();
        if (kt + 2 < KT) {
            int sn = s + 2; if (sn >= 3) sn -= 3;
            G3_LOAD(sn, (kt + 2) << 5);
        }
        const float* Am = smem + s * G3_STAGE;
        const float* Bm = Am + G3_A;
#pragma unroll
        for (int ks = 0; ks < 4; ks++) {
            int kd = (ks << 3) + a4;
            unsigned afr[2][4];
#pragma unroll
            for (int mt = 0; mt < 2; mt++) {
                int r = wr * 32 + mt * 16 + r4;
                afr[mt][0] = __float_as_uint(Am[r * 36 + kd]);
                afr[mt][1] = __float_as_uint(Am[(r + 8) * 36 + kd]);
                afr[mt][2] = __float_as_uint(Am[r * 36 + kd + 4]);
                afr[mt][3] = __float_as_uint(Am[(r + 8) * 36 + kd + 4]);
            }
#pragma unroll
            for (int nt = 0; nt < 4; nt++) {
                int n = wc * 32 + (nt << 3) + r4;
                unsigned b0 = __float_as_uint(Bm[kd * 72 + n]);
                unsigned b1 = __float_as_uint(Bm[(kd + 4) * 72 + n]);
#pragma unroll
                for (int mt = 0; mt < 2; mt++) MMA_TF32(acc[mt][nt], afr[mt], b0, b1);
            }
        }
        __syncthreads();
        s++; if (s >= 3) s -= 3;
    }
#undef G3_LOAD
}

__device__ __forceinline__ void gemm3_store(
        float acc[2][4][4], const float* __restrict__ bias, float* __restrict__ C,
        int N, int bm, int bn, int mode) {
    int tid = threadIdx.x, lane = tid & 31, w = tid >> 5;
    int wr = w >> 1, wc = w & 1;
    int r4 = lane >> 2, a4 = lane & 3;
#pragma unroll
    for (int mt = 0; mt < 2; mt++) {
        int row = bm + wr * 32 + mt * 16 + r4;
#pragma unroll
        for (int nt = 0; nt < 4; nt++) {
            int col = bn + wc * 32 + (nt << 3) + (a4 << 1);
            float bv0 = 0.f, bv1 = 0.f;
            if (mode >= 1) { bv0 = bias[col]; bv1 = bias[col + 1]; }
            float c0 = acc[mt][nt][0] + bv0, c1 = acc[mt][nt][1] + bv1;
            float c2 = acc[mt][nt][2] + bv0, c3 = acc[mt][nt][3] + bv1;
            if (mode == 2) {
                c0 = fmaxf(c0, 0.f); c1 = fmaxf(c1, 0.f);
                c2 = fmaxf(c2, 0.f); c3 = fmaxf(c3, 0.f);
            }
            *(float2*)(C + (size_t)row * N + col)       = make_float2(c0, c1);
            *(float2*)(C + (size_t)(row + 8) * N + col) = make_float2(c2, c3);
        }
    }
}

__global__ void __launch_bounds__(128) gemm3(
        const float* __restrict__ A, const float* __restrict__ B,
        const float* __restrict__ bias, float* __restrict__ C,
        int M, int N, int K, int mode) {
    float acc[2][4][4];
    int bm = blockIdx.y << 6, bn = blockIdx.x << 6;
    gemm3_core(A, B, N, K, bm, bn, acc);
    gemm3_store(acc, bias, C, N, bm, bn, mode);
}

__global__ void __launch_bounds__(128) gemm3_qkv(
        const float* __restrict__ A,
        const float* __restrict__ Wq, const float* __restrict__ Wk,
        const float* __restrict__ Wv,
        float* __restrict__ q, float* __restrict__ k, float* __restrict__ v) {
    const float* B; float* C;
    if (blockIdx.z == 0)      { B = Wq; C = q; }
    else if (blockIdx.z == 1) { B = Wk; C = k; }
    else                      { B = Wv; C = v; }
    float acc[2][4][4];
    int bm = blockIdx.y << 6, bn = blockIdx.x << 6;
    gemm3_core(A, B, Dm, Dm, bm, bn, acc);
    gemm3_store(acc, nullptr, C, Dm, bm, bn, 0);
}

// ---------------------------------------------------------------------------
// Reconstruction loss GEMM (gemm3 core) with L1 epilogue
// ---------------------------------------------------------------------------
__global__ void __launch_bounds__(128) recgemm(
        const float* __restrict__ hd, const float* __restrict__ W2,
        const float* __restrict__ b2, const float* __restrict__ pts,
        float* __restrict__ part) {
    float acc[2][4][4];
    int bm = blockIdx.y << 6, bn = blockIdx.x << 6;
    gemm3_core(hd, W2, ENCIN, 128, bm, bn, acc);

    int tid = threadIdx.x, lane = tid & 31, w = tid >> 5;
    int wr = w >> 1, wc = w & 1;
    int r4 = lane >> 2, a4 = lane & 3;
    float local = 0.f;
#pragma unroll
    for (int mt = 0; mt < 2; mt++) {
        int row = bm + wr * 32 + mt * 16 + r4;
#pragma unroll
        for (int nt = 0; nt < 4; nt++) {
            int col = bn + wc * 32 + (nt << 3) + (a4 << 1);
            float bv0 = b2[col], bv1 = b2[col + 1];
            float2 p0 = *(const float2*)(pts + (size_t)row * ENCIN + col);
            float2 p1 = *(const float2*)(pts + (size_t)(row + 8) * ENCIN + col);
            local += fabsf(p0.x - (acc[mt][nt][0] + bv0));
            local += fabsf(p0.y - (acc[mt][nt][1] + bv1));
            local += fabsf(p1.x - (acc[mt][nt][2] + bv0));
            local += fabsf(p1.y - (acc[mt][nt][3] + bv1));
        }
    }
    float s = blockSum128(local);
    if (tid == 0) part[blockIdx.y * gridDim.x + blockIdx.x] = s;
}

// ---------------------------------------------------------------------------
// Fused GEMM + residual + LayerNorm (R15-proven): BM=32, BN=256, BK=64,
// 2-stage, 8 warps, grid 128.
// ---------------------------------------------------------------------------
#define GLN_A (32 * 68)
#define GLN_B (64 * 264)
#define GLN_STAGE (GLN_A + GLN_B)
#define GLN_SMEM (2 * GLN_STAGE * 4)

__global__ void __launch_bounds__(256) gemmLN(
        const float* __restrict__ A, const float* __restrict__ W,
        const float* __restrict__ bias, float* __restrict__ z,
        const float* __restrict__ gam, const float* __restrict__ bet, int K) {
    extern __shared__ float smem[];
    int tid = threadIdx.x, lane = tid & 31, w = tid >> 5;
    int wr = w >> 2, wc = w & 3;
    int r4 = lane >> 2, a4 = lane & 3;
    int bm = blockIdx.x << 5;

    float acc[8][4];
#pragma unroll
    for (int nt = 0; nt < 8; nt++)
#pragma unroll
        for (int c = 0; c < 4; c++) acc[nt][c] = 0.f;

#define GLN_LOAD(sidx, k0)                                                    \
    {                                                                         \
        float* Ad = smem + (sidx) * GLN_STAGE;                                \
        float* Bd = Ad + GLN_A;                                               \
        _Pragma("unroll")                                                     \
        for (int j = 0; j < 2; j++) {                                         \
            int idx = tid + (j << 8);                                         \
            int row = idx >> 4, cc = (idx & 15) << 2;                         \
            cpasync16(&Ad[row * 68 + cc],                                     \
                      A + (size_t)(bm + row) * K + (k0) + cc);                \
        }                                                                     \
        _Pragma("unroll")                                                     \
        for (int j = 0; j < 16; j++) {                                        \
            int idx = tid + (j << 8);                                         \
            int row = idx >> 6, cc = (idx & 63) << 2;                         \
            cpasync16(&Bd[row * 264 + cc],                                    \
                      W + (size_t)((k0) + row) * Dm + cc);                    \
        }                                                                     \
        asm volatile("cp.async.commit_group;");                               \
    }

    int KT = K >> 6;
    GLN_LOAD(0, 0);

    int s = 0;
    for (int kt = 0; kt < KT; kt++) {
        if (kt + 1 < KT) {
            GLN_LOAD(s ^ 1, (kt + 1) << 6);
            asm volatile("cp.async.wait_group 1;");
        } else {
            asm volatile("cp.async.wait_group 0;");
        }
        __syncthreads();
        const float* Am = smem + s * GLN_STAGE;
        const float* Bm = Am + GLN_A;
#pragma unroll
        for (int ks = 0; ks < 8; ks++) {
            int kd = (ks << 3) + a4;
            unsigned afr[4];
            int r = wr * 16 + r4;
            afr[0] = __float_as_uint(Am[r * 68 + kd]);
            afr[1] = __float_as_uint(Am[(r + 8) * 68 + kd]);
            afr[2] = __float_as_uint(Am[r * 68 + kd + 4]);
            afr[3] = __float_as_uint(Am[(r + 8) * 68 + kd + 4]);
#pragma unroll
            for (int nt = 0; nt < 8; nt++) {
                int n = wc * 64 + (nt << 3) + r4;
                unsigned b0 = __float_as_uint(Bm[kd * 264 + n]);
                unsigned b1 = __float_as_uint(Bm[(kd + 4) * 264 + n]);
                MMA_TF32(acc[nt], afr, b0, b1);
            }
        }
        __syncthreads();
        s ^= 1;
    }
#undef GLN_LOAD

    int row0 = bm + wr * 16 + r4;
    int row1 = row0 + 8;
    int rl0 = wr * 16 + r4, rl1 = rl0 + 8;
    float v0[16], v1[16];
    float s0 = 0.f, s1 = 0.f;
#pragma unroll
    for (int nt = 0; nt < 8; nt++) {
        int col = wc * 64 + (nt << 3) + (a4 << 1);
        float bb0 = 0.f, bb1 = 0.f;
        if (bias) { bb0 = bias[col]; bb1 = bias[col + 1]; }
        float2 z0 = *(const float2*)(z + (size_t)row0 * Dm + col);
        float2 z1 = *(const float2*)(z + (size_t)row1 * Dm + col);
        float a0 = acc[nt][0] + bb0 + z0.x;
        float a1 = acc[nt][1] + bb1 + z0.y;
        float a2 = acc[nt][2] + bb0 + z1.x;
        float a3 = acc[nt][3] + bb1 + z1.y;
        v0[nt * 2] = a0; v0[nt * 2 + 1] = a1;
        v1[nt * 2] = a2; v1[nt * 2 + 1] = a3;
        s0 += a0 + a1; s1 += a2 + a3;
    }
    s0 += __shfl_xor_sync(0xffffffffu, s0, 1);
    s0 += __shfl_xor_sync(0xffffffffu, s0, 2);
    s1 += __shfl_xor_sync(0xffffffffu, s1, 1);
    s1 += __shfl_xor_sync(0xffffffffu, s1, 2);
    float* red = smem;
    if (a4 == 0) { red[rl0 * 4 + wc] = s0; red[rl1 * 4 + wc] = s1; }
    __syncthreads();
    float mu0 = (red[rl0 * 4] + red[rl0 * 4 + 1] + red[rl0 * 4 + 2] + red[rl0 * 4 + 3]) * (1.f / 256.f);
    float mu1 = (red[rl1 * 4] + red[rl1 * 4 + 1] + red[rl1 * 4 + 2] + red[rl1 * 4 + 3]) * (1.f / 256.f);
    __syncthreads();
    float q0 = 0.f, q1 = 0.f;
#pragma unroll
    for (int i = 0; i < 16; i++) {
        float d0 = v0[i] - mu0, d1 = v1[i] - mu1;
        q0 += d0 * d0; q1 += d1 * d1;
    }
    q0 += __shfl_xor_sync(0xffffffffu, q0, 1);
    q0 += __shfl_xor_sync(0xffffffffu, q0, 2);
    q1 += __shfl_xor_sync(0xffffffffu, q1, 1);
    q1 += __shfl_xor_sync(0xffffffffu, q1, 2);
    if (a4 == 0) { red[rl0 * 4 + wc] = q0; red[rl1 * 4 + wc] = q1; }
    __syncthreads();
    float var0 = (red[rl0 * 4] + red[rl0 * 4 + 1] + red[rl0 * 4 + 2] + red[rl0 * 4 + 3]) * (1.f / 256.f);
    float var1 = (red[rl1 * 4] + red[rl1 * 4 + 1] + red[rl1 * 4 + 2] + red[rl1 * 4 + 3]) * (1.f / 256.f);
    float rs0 = rsqrtf(var0 + 1e-5f), rs1 = rsqrtf(var1 + 1e-5f);
#pragma unroll
    for (int nt = 0; nt < 8; nt++) {
        int col = wc * 64 + (nt << 3) + (a4 << 1);
        float g0 = gam[col], g1 = gam[col + 1];
        float be0 = bet[col], be1 = bet[col + 1];
        *(float2*)(z + (size_t)row0 * Dm + col) = make_float2(
            (v0[nt * 2] - mu0) * rs0 * g0 + be0,
            (v0[nt * 2 + 1] - mu0) * rs0 * g1 + be1);
        *(float2*)(z + (size_t)row1 * Dm + col) = make_float2(
            (v1[nt * 2] - mu1) * rs1 * g0 + be0,
            (v1[nt * 2 + 1] - mu1) * rs1 * g1 + be1);
    }
}

// ---------------------------------------------------------------------------
// TF32-MMA flash attention, chunked-PV small-smem (proven R10)
// ---------------------------------------------------------------------------
#define AT4_SMEM_FLOATS (64 * 36 + 128 * 36 + 128 * 40 + 4 * 192)
#define AT4_SMEM_BYTES  (AT4_SMEM_FLOATS * 4)

__global__ void __launch_bounds__(128, 4) attn4(
        const float* __restrict__ qg, const float* __restrict__ kg,
        const float* __restrict__ vg, float* __restrict__ og) {
    extern __shared__ float sm[];
    float* Qs = sm;
    float* Ks = Qs + 64 * 36;
    float* Vs = Ks + 128 * 36;
    float* Ps = Vs + 128 * 40;

    int bh = blockIdx.y, b = bh >> 3, h = bh & 7;
    int qt = blockIdx.x;
    int tid = threadIdx.x, w = tid >> 5, lane = tid & 31;
    int r4 = lane >> 2, a4 = lane & 3;
    size_t base = (size_t)b * SEQ * Dm + h * 32;
    const float scale = 0.17677669529663687f;

    for (int i = tid; i < 512; i += 128) {
        int row = i >> 3, c4 = (i & 7) << 2;
        float4 t = *(const float4*)(qg + base + (size_t)(qt * 64 + row) * Dm + c4);
        t.x *= scale; t.y *= scale; t.z *= scale; t.w *= scale;
        *(float4*)&Qs[row * 36 + c4] = t;
    }

    int q0 = w * 16;
    float* Pws = Ps + w * 192;
    float m0 = -1e30f, m1 = -1e30f, l0 = 0.f, l1 = 0.f;
    float oacc[4][4];
#pragma unroll
    for (int nt = 0; nt < 4; nt++)
#pragma unroll
        for (int c = 0; c < 4; c++) oacc[nt][c] = 0.f;

    for (int c = 0; c < 4; c++) {
        __syncthreads();
        for (int i = tid; i < 1024; i += 128) {
            int row = i >> 3, c4 = (i & 7) << 2;
            size_t goff = base + (size_t)(c * 128 + row) * Dm + c4;
            float4 tk = *(const float4*)(kg + goff);
            *(float4*)&Ks[row * 36 + c4] = tk;
            float4 tv = *(const float4*)(vg + goff);
            *(float4*)&Vs[row * 40 + c4] = tv;
        }
        __syncthreads();

        float S[16][4];
#pragma unroll
        for (int nt = 0; nt < 16; nt++)
#pragma unroll
            for (int j = 0; j < 4; j++) S[nt][j] = 0.f;

#pragma unroll
        for (int ks = 0; ks < 4; ks++) {
            int kd = (ks << 3) + a4;
            unsigned aq[4];
            int r = q0 + r4;
            aq[0] = __float_as_uint(Qs[r * 36 + kd]);
            aq[1] = __float_as_uint(Qs[(r + 8) * 36 + kd]);
            aq[2] = __float_as_uint(Qs[r * 36 + kd + 4]);
            aq[3] = __float_as_uint(Qs[(r + 8) * 36 + kd + 4]);
#pragma unroll
            for (int nt = 0; nt < 16; nt++) {
                int key = (nt << 3) + r4;
                unsigned b0 = __float_as_uint(Ks[key * 36 + kd]);
                unsigned b1 = __float_as_uint(Ks[key * 36 + kd + 4]);
                MMA_TF32(S[nt], aq, b0, b1);
            }
        }

        float mxa = -1e30f, mxb = -1e30f;
#pragma unroll
        for (int nt = 0; nt < 16; nt++) {
            mxa = fmaxf(mxa, fmaxf(S[nt][0], S[nt][1]));
            mxb = fmaxf(mxb, fmaxf(S[nt][2], S[nt][3]));
        }
#pragma unroll
        for (int off = 1; off < 4; off <<= 1) {
            mxa = fmaxf(mxa, __shfl_xor_sync(0xffffffffu, mxa, off));
            mxb = fmaxf(mxb, __shfl_xor_sync(0xffffffffu, mxb, off));
        }
        float mna = fmaxf(m0, mxa), mnb = fmaxf(m1, mxb);
        float corra = __expf(m0 - mna), corrb = __expf(m1 - mnb);
        float sa = 0.f, sb = 0.f;
#pragma unroll
        for (int nt = 0; nt < 16; nt++) {
            float p0 = __expf(S[nt][0] - mna);
            float p1 = __expf(S[nt][1] - mna);
            float p2 = __expf(S[nt][2] - mnb);
            float p3 = __expf(S[nt][3] - mnb);
            sa += p0 + p1; sb += p2 + p3;
            S[nt][0] = p0; S[nt][1] = p1; S[nt][2] = p2; S[nt][3] = p3;
        }
#pragma unroll
        for (int off = 1; off < 4; off <<= 1) {
            sa += __shfl_xor_sync(0xffffffffu, sa, off);
            sb += __shfl_xor_sync(0xffffffffu, sb, off);
        }
        l0 = l0 * corra + sa; m0 = mna;
        l1 = l1 * corrb + sb; m1 = mnb;
#pragma unroll
        for (int nt = 0; nt < 4; nt++) {
            oacc[nt][0] *= corra; oacc[nt][1] *= corra;
            oacc[nt][2] *= corrb; oacc[nt][3] *= corrb;
        }
        __syncwarp();

#pragma unroll
        for (int ks = 0; ks < 16; ks++) {
            *(float2*)&Pws[r4 * 12 + (a4 << 1)]       = make_float2(S[ks][0], S[ks][1]);
            *(float2*)&Pws[(r4 + 8) * 12 + (a4 << 1)] = make_float2(S[ks][2], S[ks][3]);
            __syncwarp();
            unsigned ap[4];
            ap[0] = __float_as_uint(Pws[r4 * 12 + a4]);
            ap[1] = __float_as_uint(Pws[(r4 + 8) * 12 + a4]);
            ap[2] = __float_as_uint(Pws[r4 * 12 + a4 + 4]);
            ap[3] = __float_as_uint(Pws[(r4 + 8) * 12 + a4 + 4]);
            int keyb = ks << 3;
#pragma unroll
            for (int nt = 0; nt < 4; nt++) {
                int dim = (nt << 3) + r4;
                unsigned b0 = __float_as_uint(Vs[(keyb + a4) * 40 + dim]);
                unsigned b1 = __float_as_uint(Vs[(keyb + a4 + 4) * 40 + dim]);
                MMA_TF32(oacc[nt], ap, b0, b1);
            }
            __syncwarp();
        }
    }

    float inva = 1.f / l0, invb = 1.f / l1;
    int rowa = qt * 64 + q0 + r4;
#pragma unroll
    for (int nt = 0; nt < 4; nt++) {
        int col = (nt << 3) + (a4 << 1);
        *(float2*)(og + base + (size_t)rowa * Dm + col) =
            make_float2(oacc[nt][0] * inva, oacc[nt][1] * inva);
        *(float2*)(og + base + (size_t)(rowa + 8) * Dm + col) =
            make_float2(oacc[nt][2] * invb, oacc[nt][3] * invb);
    }
}

// ---------------------------------------------------------------------------
// fp32 split-K GEMM (encoder path — exact)
// ---------------------------------------------------------------------------
__global__ void __launch_bounds__(256) gemm_splitk(
        const float* __restrict__ A, int lda, const float* __restrict__ B, int ldb,
        float* __restrict__ Cp, int M, int N, int Kchunk) {
    __shared__ float As[16][65];
    __shared__ float Bs[16][64];
    int zc = blockIdx.z;
    A  += zc * Kchunk;
    B  += (size_t)zc * Kchunk * ldb;
    Cp += (size_t)zc * M * N;
    int tid = threadIdx.x;
    int bm = blockIdx.y << 6, bn = blockIdx.x << 6;
    int tx = tid & 15, ty = tid >> 4;
    int arow = tid >> 2, acol = (tid & 3) << 2;
    int brow = tid >> 4, bcol = (tid & 15) << 2;

    float acc[4][4] = {};
    for (int k0 = 0; k0 < Kchunk; k0 += 16) {
        float4 a4 = *(const float4*)(A + (size_t)(bm + arow) * lda + k0 + acol);
        As[acol + 0][arow] = a4.x; As[acol + 1][arow] = a4.y;
        As[acol + 2][arow] = a4.z; As[acol + 3][arow] = a4.w;
        float4 b4 = *(const float4*)(B + (size_t)(k0 + brow) * ldb + bn + bcol);
        *(float4*)&Bs[brow][bcol] = b4;
        __syncthreads();
#pragma unroll
        for (int kk = 0; kk < 16; kk++) {
            float a0 = As[kk][(ty << 2) + 0], a1 = As[kk][(ty << 2) + 1];
            float a2 = As[kk][(ty << 2) + 2], a3 = As[kk][(ty << 2) + 3];
            float4 b = *(const float4*)&Bs[kk][tx << 2];
            acc[0][0] += a0 * b.x; acc[0][1] += a0 * b.y; acc[0][2] += a0 * b.z; acc[0][3] += a0 * b.w;
            acc[1][0] += a1 * b.x; acc[1][1] += a1 * b.y; acc[1][2] += a1 * b.z; acc[1][3] += a1 * b.w;
            acc[2][0] += a2 * b.x; acc[2][1] += a2 * b.y; acc[2][2] += a2 * b.z; acc[2][3] += a2 * b.w;
            acc[3][0] += a3 * b.x; acc[3][1] += a3 * b.y; acc[3][2] += a3 * b.z; acc[3][3] += a3 * b.w;
        }
        __syncthreads();
    }
#pragma unroll
    for (int i = 0; i < 4; i++) {
        float4 r = make_float4(acc[i][0], acc[i][1], acc[i][2], acc[i][3]);
        *(float4*)(Cp + (size_t)(bm + (ty << 2) + i) * N + bn + (tx << 2)) = r;
    }
}

// ---------------------------------------------------------------------------
// Fused enc_reduce + low head (proven R10): one CTA per point.
// ---------------------------------------------------------------------------
__global__ void __launch_bounds__(128) enclow_kernel(
        const float* __restrict__ part, const float* __restrict__ eb1,
        const float* __restrict__ eW2, const float* __restrict__ eb2,
        const float* __restrict__ dW1, const float* __restrict__ db1,
        const float* __restrict__ ctr,
        float* __restrict__ low, float* __restrict__ hd,
        int* __restrict__ idxp, float* __restrict__ dsq) {
    int n = blockIdx.x, m = threadIdx.x;
    __shared__ float lo_sh[2];
    float s = eb1[m];
#pragma unroll
    for (int ch = 0; ch < 32; ch++) s += part[ch * (Np * 128) + n * 128 + m];
    float hv = fmaxf(s, 0.f);

    float pa0 = hv * eW2[m * 2];
    float pa1 = hv * eW2[m * 2 + 1];
    float a0 = blockSum128(pa0);
    float a1 = blockSum128(pa1);
    if (m == 0) {
        float lo0 = 1.f / (1.f + expf(-(a0 + eb2[0])));
        float lo1 = 1.f / (1.f + expf(-(a1 + eb2[1])));
        lo_sh[0] = lo0; lo_sh[1] = lo1;
        low[n * 2 + 0] = lo0;
        low[n * 2 + 1] = lo1;
        int best = 0; float bd = 3.4e38f;
#pragma unroll
        for (int c = 0; c < Kc; c++) {
            float dx = lo0 - ctr[2 * c], dy = lo1 - ctr[2 * c + 1];
            float d2 = dx * dx + dy * dy;
            if (d2 < bd) { bd = d2; best = c; }
        }
        idxp[n] = best;
        dsq[n] = bd;
    }
    __syncthreads();
    float lo0 = lo_sh[0], lo1 = lo_sh[1];
    hd[n * 128 + m] = fmaxf(lo0 * dW1[m] + lo1 * dW1[128 + m] + db1[m], 0.f);
}

// ---------------------------------------------------------------------------
// Final losses + output
// ---------------------------------------------------------------------------
__global__ void final_kernel(const float* __restrict__ dsq, const int* __restrict__ idxp,
                             const float* __restrict__ low, const float* __restrict__ recpart,
                             float* __restrict__ out, int out_size) {
    __shared__ float sums[Kc], cnts[Kc];
    int tid = threadIdx.x;
    float d = dsq[tid];
    int my = idxp[tid];

    float inter = blockSum256(d) * (1.f / 256.f);

    if (tid < Kc) { sums[tid] = 0.f; cnts[tid] = 0.f; }
    __syncthreads();
    atomicAdd(&sums[my], d);
    atomicAdd(&cnts[my], 1.f);
    __syncthreads();

    bool mem = false;
    for (int j = 0; j < 256; j++) {
        if (idxp[j] == tid) { mem = true; break; }
    }
    float arr = mem ? 100.f : 0.f;

    float se = blockSum256(expf(arr - 100.f));
    float lse = logf(se) + 100.f;
    float logp = arr - lse;

    float klsum = blockSum256(-logf(256.f) - logp);
    float kl = klsum * (1.f / (256.f * 256.f));

    float rec = blockSum256(recpart[tid]) * (1.f / (256.f * 4096.f));

    if (tid == 0) {
        float intra = 0.f, ne = 0.f;
#pragma unroll
        for (int c = 0; c < Kc; c++) {
            if (cnts[c] > 0.f) { intra += sums[c] / fmaxf(cnts[c], 1.f); ne += 1.f; }
        }
        intra /= fmaxf(ne, 1.f);
        float loss = inter + intra + kl + rec;
        if (out_size > 0) out[0] = loss;
        if (out_size > 1) out[1] = kl;
    }
    if (2 + tid < out_size) out[2 + tid] = (float)my;
    int p0 = 258 + 2 * tid;
    if (p0 < out_size)     out[p0]     = low[2 * tid];
    if (p0 + 1 < out_size) out[p0 + 1] = low[2 * tid + 1];
}

// ---------------------------------------------------------------------------
// Host launcher
// ---------------------------------------------------------------------------
extern "C" void kernel_launch(void* const* d_in, const int* in_sizes, int n_in,
                              void* d_out, int out_size) {
    const float* x_seg  = (const float*)d_in[1];
    const float* emb_W  = (const float*)d_in[2];
    const float* emb_b  = (const float*)d_in[3];
    const float* Wq     = (const float*)d_in[4];
    const float* Wk     = (const float*)d_in[5];
    const float* Wv     = (const float*)d_in[6];
    const float* Wo     = (const float*)d_in[7];
    const float* W1     = (const float*)d_in[8];
    const float* b1     = (const float*)d_in[9];
    const float* W2     = (const float*)d_in[10];
    const float* b2     = (const float*)d_in[11];
    const float* ln1_g  = (const float*)d_in[12];
    const float* ln1_b  = (const float*)d_in[13];
    const float* ln2_g  = (const float*)d_in[14];
    const float* ln2_b  = (const float*)d_in[15];
    const float* enc_W1 = (const float*)d_in[16];
    const float* enc_b1 = (const float*)d_in[17];
    const float* enc_W2 = (const float*)d_in[18];
    const float* enc_b2 = (const float*)d_in[19];
    const float* dec_W1 = (const float*)d_in[20];
    const float* dec_b1 = (const float*)d_in[21];
    const float* dec_W2 = (const float*)d_in[22];
    const float* dec_b2 = (const float*)d_in[23];
    const float* centers = (const float*)d_in[24];

    float *z, *q, *k, *v, *o, *h1, *encpart, *low, *hd, *dsq, *recpart;
    int* idxp;
    cudaGetSymbolAddress((void**)&z,   g_z);
    cudaGetSymbolAddress((void**)&q,   g_q);
    cudaGetSymbolAddress((void**)&k,   g_k);
    cudaGetSymbolAddress((void**)&v,   g_v);
    cudaGetSymbolAddress((void**)&o,   g_o);
    cudaGetSymbolAddress((void**)&h1,  g_h1);
    cudaGetSymbolAddress((void**)&encpart, g_encpart);
    cudaGetSymbolAddress((void**)&low, g_low);
    cudaGetSymbolAddress((void**)&hd,  g_hd);
    cudaGetSymbolAddress((void**)&dsq, g_dsq);
    cudaGetSymbolAddress((void**)&idxp, g_idx);
    cudaGetSymbolAddress((void**)&recpart, g_recpart);

    cudaFuncSetAttribute(gemm3,     cudaFuncAttributeMaxDynamicSharedMemorySize, GEMM3_SMEM);
    cudaFuncSetAttribute(gemm3_qkv, cudaFuncAttributeMaxDynamicSharedMemorySize, GEMM3_SMEM);
    cudaFuncSetAttribute(recgemm,   cudaFuncAttributeMaxDynamicSharedMemorySize, GEMM3_SMEM);
    cudaFuncSetAttribute(gemmLN,    cudaFuncAttributeMaxDynamicSharedMemorySize, GLN_SMEM);
    cudaFuncSetAttribute(attn4,     cudaFuncAttributeMaxDynamicSharedMemorySize, AT4_SMEM_BYTES);

    embed_kernel<<<TOK, 256>>>(x_seg, emb_W, emb_b, z);

    for (int l = 0; l < 2; l++) {
        size_t wo = (size_t)l * Dm * Dm;
        gemm3_qkv<<<dim3(4, 64, 3), 128, GEMM3_SMEM>>>(z, Wq + wo, Wk + wo, Wv + wo, q, k, v);
        attn4<<<dim3(8, 64), 128, AT4_SMEM_BYTES>>>(q, k, v, o);
        gemmLN<<<128, 256, GLN_SMEM>>>(o, Wo + wo, nullptr, z,
                                       ln1_g + l * Dm, ln1_b + l * Dm, Dm);
        gemm3<<<dim3(16, 64), 128, GEMM3_SMEM>>>(z, W1 + (size_t)l * Dm * FFd, b1 + l * FFd,
                                                 h1, TOK, FFd, Dm, 2);
        gemmLN<<<128, 256, GLN_SMEM>>>(h1, W2 + (size_t)l * FFd * Dm, b2 + l * Dm, z,
                                       ln2_g + l * Dm, ln2_b + l * Dm, FFd);
    }

    gemm_splitk<<<dim3(2, 4, 32), 256>>>(z, ENCIN, enc_W1, 128, encpart, Np, 128, 128);
    enclow_kernel<<<Np, 128>>>(encpart, enc_b1, enc_W2, enc_b2, dec_W1, dec_b1,
                               centers, low, hd, idxp, dsq);
    recgemm<<<dim3(64, 4), 128, GEMM3_SMEM>>>(hd, dec_W2, dec_b2, z, recpart);
    final_kernel<<<1, 256>>>(dsq, idxp, low, recpart, (float*)d_out, out_size);
}